// round 11
// baseline (speedup 1.0000x reference)
#include <cuda_runtime.h>
#include <cuda_fp16.h>
#include <cstdint>

#define DIN 512
#define DH  256
#define GNUM 128
#define NMAX 20000
#define EMAX 320000
#define CAP  96          // padded-CSR slots per node

// ---- scratch (static __device__ globals; zero-initialized at load) ----
__device__ __half g_y16[NMAX * DH];    // messages y = (A@W)*dinv[row], fp16
__device__ float  g_h[NMAX * DH];      // layer-1 output (tf32-grid, GEMM-2 input)
__device__ float  g_xr[NMAX * DIN];    // x pre-rounded to tf32 grid
__device__ float  g_w1r[DIN * DH];     // W1 pre-rounded
__device__ float  g_w2r[DH * DH];      // W2 pre-rounded
__device__ int    g_icnt[NMAX];        // in-degree (excl. self); cleared by gather<1>
__device__ int    g_eslot[NMAX * CAP]; // padded CSR: src per incoming edge
__device__ float  g_pool[GNUM * DH];   // cleared by k_fc after read
__device__ float  g_cnt[GNUM];         // cleared by k_fc after read

// ================= helpers =================
__device__ __forceinline__ float tf32r(float x) {
    uint32_t u;
    asm("cvt.rna.tf32.f32 %0, %1;" : "=r"(u) : "f"(x));
    return __uint_as_float(u);
}

__device__ __forceinline__ uint32_t smem_u32(const void* p) {
    uint32_t a;
    asm("{ .reg .u64 t; cvta.to.shared.u64 t, %1; cvt.u32.u64 %0, t; }" : "=r"(a) : "l"(p));
    return a;
}

__device__ __forceinline__ void mma_tf32(float* c, const uint32_t* a, const uint32_t* b) {
    asm volatile("mma.sync.aligned.m16n8k8.row.col.f32.tf32.tf32.f32 "
        "{%0,%1,%2,%3}, {%4,%5,%6,%7}, {%8,%9}, {%0,%1,%2,%3};"
        : "+f"(c[0]), "+f"(c[1]), "+f"(c[2]), "+f"(c[3])
        : "r"(a[0]), "r"(a[1]), "r"(a[2]), "r"(a[3]), "r"(b[0]), "r"(b[1]));
}

__device__ __forceinline__ void addh4(float* a, uint2 u) {
    float2 f0 = __half22float2(*(const __half2*)&u.x);
    float2 f1 = __half22float2(*(const __half2*)&u.y);
    a[0] += f0.x; a[1] += f0.y; a[2] += f1.x; a[3] += f1.y;
}

// ================= fused prep: CSR fill + tf32-round x, W1, W2 =================
__global__ void k_prep(const int* __restrict__ src, const int* __restrict__ dst,
                       const float* __restrict__ x, const float* __restrict__ W1,
                       const float* __restrict__ W2, int E, int N)
{
    const int FILL_B = (E + 255) / 256;
    const int XR_Q   = N * DIN / 4;
    const int XR_B   = (XR_Q + 255) / 256;
    const int W1_B   = (DIN * DH / 4) / 256;
    const int b = blockIdx.x;

    if (b < FILL_B) {
        int e = b * 256 + threadIdx.x;
        if (e < E) {
            int d = dst[e];
            int pos = atomicAdd(&g_icnt[d], 1);
            if (pos < CAP) g_eslot[d * CAP + pos] = src[e];
        }
    } else if (b < FILL_B + XR_B) {
        int q = (b - FILL_B) * 256 + threadIdx.x;
        if (q < XR_Q) {
            float4 v = ((const float4*)x)[q];
            v.x = tf32r(v.x); v.y = tf32r(v.y); v.z = tf32r(v.z); v.w = tf32r(v.w);
            ((float4*)g_xr)[q] = v;
        }
    } else if (b < FILL_B + XR_B + W1_B) {
        int q = (b - FILL_B - XR_B) * 256 + threadIdx.x;
        float4 v = ((const float4*)W1)[q];
        v.x = tf32r(v.x); v.y = tf32r(v.y); v.z = tf32r(v.z); v.w = tf32r(v.w);
        ((float4*)g_w1r)[q] = v;
    } else {
        int q = (b - FILL_B - XR_B - W1_B) * 256 + threadIdx.x;
        if (q < DH * DH / 4) {
            float4 v = ((const float4*)W2)[q];
            v.x = tf32r(v.x); v.y = tf32r(v.y); v.z = tf32r(v.z); v.w = tf32r(v.w);
            ((float4*)g_w2r)[q] = v;
        }
    }
}

// ================= TF32 GEMM, cp.async 3-stage: g_y16 = half((A @ W) * dinv[row]) =================
// CTA 160 x 256 (full N), 640 threads (20 warps, 5x4), warptile 32x64.
#define AST 36
#define BST 264
#define A_F (160 * AST)
#define B_F (32 * BST)
#define STG_F (A_F + B_F)
#define SMEM_GEMM_BYTES (3 * STG_F * 4)

template<int K>
__global__ void __launch_bounds__(640, 1)
k_gemm_cp(const float* __restrict__ A, const float* __restrict__ W, int M)
{
    extern __shared__ float sm[];
    const uint32_t sbase = smem_u32(sm);

    const int tid = threadIdx.x;
    const int wid = tid >> 5;
    const int lid = tid & 31;
    const int gid = lid >> 2;
    const int tig = lid & 3;
    const int warpM = wid % 5;
    const int warpN = wid / 5;
    const int rowBase = blockIdx.x * 160;
    constexpr int NC = K / 32;

    float C[2][8][4];
    #pragma unroll
    for (int mt = 0; mt < 2; mt++)
        #pragma unroll
        for (int nt = 0; nt < 8; nt++)
            #pragma unroll
            for (int i = 0; i < 4; i++) C[mt][nt][i] = 0.f;

    auto stage = [&](int buf, int c) {
        uint32_t Asb = sbase + buf * (STG_F * 4);
        uint32_t Bsb = Asb + A_F * 4;
        #pragma unroll
        for (int i = 0; i < 2; i++) {
            int idx = tid + i * 640;
            int m = idx >> 3, k4 = (idx & 7) << 2;
            const float* s = A + (size_t)(rowBase + m) * K + c * 32 + k4;
            uint32_t d = Asb + (uint32_t)(m * AST + k4) * 4;
            int sz = (rowBase + m < M) ? 16 : 0;
            asm volatile("cp.async.cg.shared.global [%0], [%1], 16, %2;"
                         :: "r"(d), "l"(s), "r"(sz) : "memory");
        }
        #pragma unroll
        for (int i = 0; i < 4; i++) {
            int idx = tid + i * 640;
            if (idx < 2048) {
                int k = idx >> 6, n4 = (idx & 63) << 2;
                const float* s = W + (size_t)(c * 32 + k) * DH + n4;
                uint32_t d = Bsb + (uint32_t)(k * BST + n4) * 4;
                asm volatile("cp.async.cg.shared.global [%0], [%1], 16;"
                             :: "r"(d), "l"(s) : "memory");
            }
        }
    };

    stage(0, 0);
    asm volatile("cp.async.commit_group;" ::: "memory");
    if (NC > 1) {
        stage(1, 1);
        asm volatile("cp.async.commit_group;" ::: "memory");
    }

    for (int c = 0; c < NC; c++) {
        if (c + 1 < NC) asm volatile("cp.async.wait_group 1;" ::: "memory");
        else            asm volatile("cp.async.wait_group 0;" ::: "memory");
        __syncthreads();
        if (c + 2 < NC) {
            stage((c + 2) % 3, c + 2);
            asm volatile("cp.async.commit_group;" ::: "memory");
        }

        const float* As = sm + (c % 3) * STG_F;
        const float* Bs = As + A_F;

        #pragma unroll
        for (int ks = 0; ks < 4; ks++) {
            const int kk = ks * 8 + tig;
            uint32_t a[2][4];
            #pragma unroll
            for (int mt = 0; mt < 2; mt++) {
                int mr = warpM * 32 + mt * 16 + gid;
                a[mt][0] = __float_as_uint(As[mr * AST + kk]);
                a[mt][1] = __float_as_uint(As[(mr + 8) * AST + kk]);
                a[mt][2] = __float_as_uint(As[mr * AST + kk + 4]);
                a[mt][3] = __float_as_uint(As[(mr + 8) * AST + kk + 4]);
            }
            #pragma unroll
            for (int nt = 0; nt < 8; nt++) {
                int nc = warpN * 64 + nt * 8 + gid;
                uint32_t b[2];
                b[0] = __float_as_uint(Bs[kk * BST + nc]);
                b[1] = __float_as_uint(Bs[(kk + 4) * BST + nc]);
                mma_tf32(C[0][nt], a[0], b);
                mma_tf32(C[1][nt], a[1], b);
            }
        }
    }

    // epilogue: dinv = rsqrt(1 + indeg), scale, write fp16 messages
    #pragma unroll
    for (int mt = 0; mt < 2; mt++) {
        int gr0 = rowBase + warpM * 32 + mt * 16 + gid;
        int gr1 = gr0 + 8;
        float d0 = (gr0 < M) ? rsqrtf(1.0f + (float)g_icnt[gr0]) : 0.f;
        float d1 = (gr1 < M) ? rsqrtf(1.0f + (float)g_icnt[gr1]) : 0.f;
        #pragma unroll
        for (int nt = 0; nt < 8; nt++) {
            int col = warpN * 64 + nt * 8 + tig * 2;
            if (gr0 < M)
                *(__half2*)&g_y16[(size_t)gr0 * DH + col] =
                    __floats2half2_rn(C[mt][nt][0] * d0, C[mt][nt][1] * d0);
            if (gr1 < M)
                *(__half2*)&g_y16[(size_t)gr1 * DH + col] =
                    __floats2half2_rn(C[mt][nt][2] * d1, C[mt][nt][3] * d1);
        }
    }
}

// ================= CSR gather: 64 threads/node (proven shape), fp16 loads =================
// Each thread covers 4 columns = uint2 (8B). 8-deep index-batched loads, fp32 accumulate.
template<bool LAYER2>
__global__ void __launch_bounds__(256)
k_gather(const int* __restrict__ batch, const float* __restrict__ bias, int N)
{
    __shared__ float sp[DH];
    __shared__ int sg;

    const int node = blockIdx.x * 4 + (threadIdx.x >> 6);
    const bool valid = node < N;
    const int c = (threadIdx.x & 63) << 2;

    if (LAYER2) {
        sp[threadIdx.x] = 0.f;
        if (threadIdx.x == 0) sg = batch[min(blockIdx.x * 4, N - 1)];
        __syncthreads();
    } else {
        if (!valid) return;
    }

    float acc[4] = {0.f, 0.f, 0.f, 0.f};
    int cnt0 = 0;

    if (valid) {
        cnt0 = g_icnt[node];
        const int cnt = min(cnt0, CAP);
        if (!LAYER2 && (threadIdx.x & 63) == 0)
            atomicAdd(&g_cnt[batch[node]], 1.0f);

        addh4(acc, *(const uint2*)(g_y16 + (size_t)node * DH + c));   // self loop

        const int4* ip = (const int4*)(g_eslot + node * CAP);         // CAP%4==0
        int j = 0;
        for (; j + 8 <= cnt; j += 8) {
            int4 sA = ip[j >> 2];
            int4 sB = ip[(j >> 2) + 1];
            uint2 v0 = *(const uint2*)(g_y16 + (size_t)sA.x * DH + c);
            uint2 v1 = *(const uint2*)(g_y16 + (size_t)sA.y * DH + c);
            uint2 v2 = *(const uint2*)(g_y16 + (size_t)sA.z * DH + c);
            uint2 v3 = *(const uint2*)(g_y16 + (size_t)sA.w * DH + c);
            uint2 v4 = *(const uint2*)(g_y16 + (size_t)sB.x * DH + c);
            uint2 v5 = *(const uint2*)(g_y16 + (size_t)sB.y * DH + c);
            uint2 v6 = *(const uint2*)(g_y16 + (size_t)sB.z * DH + c);
            uint2 v7 = *(const uint2*)(g_y16 + (size_t)sB.w * DH + c);
            addh4(acc, v0); addh4(acc, v1); addh4(acc, v2); addh4(acc, v3);
            addh4(acc, v4); addh4(acc, v5); addh4(acc, v6); addh4(acc, v7);
        }
        if (j + 4 <= cnt) {
            int4 sA = ip[j >> 2];
            uint2 v0 = *(const uint2*)(g_y16 + (size_t)sA.x * DH + c);
            uint2 v1 = *(const uint2*)(g_y16 + (size_t)sA.y * DH + c);
            uint2 v2 = *(const uint2*)(g_y16 + (size_t)sA.z * DH + c);
            uint2 v3 = *(const uint2*)(g_y16 + (size_t)sA.w * DH + c);
            addh4(acc, v0); addh4(acc, v1); addh4(acc, v2); addh4(acc, v3);
            j += 4;
        }
        for (; j < cnt; j++) {
            int s = g_eslot[node * CAP + j];
            addh4(acc, *(const uint2*)(g_y16 + (size_t)s * DH + c));
        }
    }

    if (!LAYER2) {
        const float dv = rsqrtf(1.0f + (float)cnt0);
        float4 b = *(const float4*)(bias + c);
        float4 r;
        r.x = tf32r(fmaxf(fmaf(acc[0], dv, b.x), 0.f));   // pre-round for GEMM2
        r.y = tf32r(fmaxf(fmaf(acc[1], dv, b.y), 0.f));
        r.z = tf32r(fmaxf(fmaf(acc[2], dv, b.z), 0.f));
        r.w = tf32r(fmaxf(fmaf(acc[3], dv, b.w), 0.f));
        *(float4*)(g_h + (size_t)node * DH + c) = r;
    } else {
        if (valid) {
            const float dv = rsqrtf(1.0f + (float)cnt0);
            float4 b = *(const float4*)(bias + c);
            float r[4];
            r[0] = fmaxf(fmaf(acc[0], dv, b.x), 0.f);
            r[1] = fmaxf(fmaf(acc[1], dv, b.y), 0.f);
            r[2] = fmaxf(fmaf(acc[2], dv, b.z), 0.f);
            r[3] = fmaxf(fmaf(acc[3], dv, b.w), 0.f);
            int g = batch[node];
            if (g == sg) {
                #pragma unroll
                for (int i = 0; i < 4; i++) atomicAdd(&sp[c + i], r[i]);
            } else {
                #pragma unroll
                for (int i = 0; i < 4; i++) atomicAdd(&g_pool[(size_t)g * DH + c + i], r[i]);
            }
            if ((threadIdx.x & 63) == 0) g_icnt[node] = 0;   // self-clean for next launch
        }
        __syncthreads();
        atomicAdd(&g_pool[(size_t)sg * DH + threadIdx.x], sp[threadIdx.x]);
    }
}

// ================= final FC (+ scratch clear) =================
__global__ void k_fc(const float* __restrict__ wfc, const float* __restrict__ bfc,
                     float* __restrict__ out)
{
    int w = (blockIdx.x * blockDim.x + threadIdx.x) >> 5;
    int lane = threadIdx.x & 31;
    if (w >= GNUM) return;
    float sum = 0.f;
    #pragma unroll
    for (int j = lane; j < DH; j += 32) {
        sum += g_pool[w * DH + j] * wfc[j];
        g_pool[w * DH + j] = 0.f;          // self-clean
    }
    #pragma unroll
    for (int o = 16; o; o >>= 1)
        sum += __shfl_xor_sync(0xffffffffu, sum, o);
    if (lane == 0) {
        float cntw = g_cnt[w];
        g_cnt[w] = 0.f;                    // self-clean
        out[w] = sum / fmaxf(cntw, 1.f) + bfc[0];
    }
}

// ================= launch =================
extern "C" void kernel_launch(void* const* d_in, const int* in_sizes, int n_in,
                              void* d_out, int out_size)
{
    const float* x     = (const float*)d_in[0];
    const int*   ei    = (const int*)  d_in[1];
    const int*   batch = (const int*)  d_in[2];
    const float* W1    = (const float*)d_in[3];
    const float* b1    = (const float*)d_in[4];
    const float* W2    = (const float*)d_in[5];
    const float* b2    = (const float*)d_in[6];
    const float* wfc   = (const float*)d_in[7];
    const float* bfc   = (const float*)d_in[8];
    float* out = (float*)d_out;

    const int N = in_sizes[2];        // 20000
    const int E = in_sizes[1] / 2;    // 320000
    const int* src = ei;
    const int* dst = ei + E;

    cudaFuncSetAttribute(k_gemm_cp<DIN>,
                         cudaFuncAttributeMaxDynamicSharedMemorySize, SMEM_GEMM_BYTES);
    cudaFuncSetAttribute(k_gemm_cp<DH>,
                         cudaFuncAttributeMaxDynamicSharedMemorySize, SMEM_GEMM_BYTES);

    // fused prep: CSR fill + tf32-round x, W1, W2
    const int FILL_B = (E + 255) / 256;
    const int XR_B   = (N * DIN / 4 + 255) / 256;
    const int W1_B   = (DIN * DH / 4) / 256;
    const int W2_B   = (DH * DH / 4) / 256;
    k_prep<<<FILL_B + XR_B + W1_B + W2_B, 256>>>(src, dst, x, W1, W2, E, N);

    float* xr;  cudaGetSymbolAddress((void**)&xr, g_xr);
    float* w1r; cudaGetSymbolAddress((void**)&w1r, g_w1r);
    float* w2r; cudaGetSymbolAddress((void**)&w2r, g_w2r);
    float* h;   cudaGetSymbolAddress((void**)&h, g_h);

    const int gemm_blocks = (N + 159) / 160;   // 125
    const int gat_blocks  = (N + 3) / 4;

    // layer 1
    k_gemm_cp<DIN><<<gemm_blocks, 640, SMEM_GEMM_BYTES>>>(xr, w1r, N);
    k_gather<false><<<gat_blocks, 256>>>(batch, b1, N);

    // layer 2
    k_gemm_cp<DH><<<gemm_blocks, 640, SMEM_GEMM_BYTES>>>(h, w2r, N);
    k_gather<true><<<gat_blocks, 256>>>(batch, b2, N);

    // fc (also clears pool/cnt for next launch)
    k_fc<<<GNUM * 32 / 128, 128>>>(wfc, bfc, out);
}

// round 12
// speedup vs baseline: 1.3939x; 1.3939x over previous
#include <cuda_runtime.h>
#include <cstdint>

#define DIN 512
#define DH  256
#define GNUM 128
#define NMAX 20000
#define EMAX 320000
#define CAP  96          // padded-CSR slots per node

// ---- scratch (static __device__ globals; zero-initialized at load) ----
__device__ float g_y[NMAX * DH];       // messages y = (A@W)*dinv[row]
__device__ float g_h[NMAX * DH];       // layer-1 output (tf32-grid, GEMM-2 input)
__device__ float g_w1r[DIN * DH];      // W1 pre-rounded to tf32 grid
__device__ float g_w2r[DH * DH];       // W2 pre-rounded
__device__ int   g_icnt[NMAX];         // in-degree (excl. self); cleared by gather<1>
__device__ int   g_eslot[NMAX * CAP];  // padded CSR: src per incoming edge
__device__ float g_pool[GNUM * DH];    // cleared by k_fc after read
__device__ float g_cnt[GNUM];          // cleared by k_fc after read

// ================= helpers =================
__device__ __forceinline__ float tf32r(float x) {
    uint32_t u;
    asm("cvt.rna.tf32.f32 %0, %1;" : "=r"(u) : "f"(x));
    return __uint_as_float(u);
}

__device__ __forceinline__ uint32_t smem_u32(const void* p) {
    uint32_t a;
    asm("{ .reg .u64 t; cvta.to.shared.u64 t, %1; cvt.u32.u64 %0, t; }" : "=r"(a) : "l"(p));
    return a;
}

__device__ __forceinline__ void mma_tf32(float* c, const uint32_t* a, const uint32_t* b) {
    asm volatile("mma.sync.aligned.m16n8k8.row.col.f32.tf32.tf32.f32 "
        "{%0,%1,%2,%3}, {%4,%5,%6,%7}, {%8,%9}, {%0,%1,%2,%3};"
        : "+f"(c[0]), "+f"(c[1]), "+f"(c[2]), "+f"(c[3])
        : "r"(a[0]), "r"(a[1]), "r"(a[2]), "r"(a[3]), "r"(b[0]), "r"(b[1]));
}

__device__ __forceinline__ void addf4(float* a, float4 v) {
    a[0] += v.x; a[1] += v.y; a[2] += v.z; a[3] += v.w;
}

// ================= fused prep: CSR fill + tf32-round W1, W2 =================
__global__ void k_prep(const int* __restrict__ src, const int* __restrict__ dst,
                       const float* __restrict__ W1, const float* __restrict__ W2, int E)
{
    const int FILL_B = (E + 255) / 256;
    const int W1_B   = (DIN * DH / 4) / 256;
    const int b = blockIdx.x;

    if (b < FILL_B) {
        int e = b * 256 + threadIdx.x;
        if (e < E) {
            int d = dst[e];
            int pos = atomicAdd(&g_icnt[d], 1);
            if (pos < CAP) g_eslot[d * CAP + pos] = src[e];
        }
    } else if (b < FILL_B + W1_B) {
        int q = (b - FILL_B) * 256 + threadIdx.x;
        float4 v = ((const float4*)W1)[q];
        v.x = tf32r(v.x); v.y = tf32r(v.y); v.z = tf32r(v.z); v.w = tf32r(v.w);
        ((float4*)g_w1r)[q] = v;
    } else {
        int q = (b - FILL_B - W1_B) * 256 + threadIdx.x;
        if (q < DH * DH / 4) {
            float4 v = ((const float4*)W2)[q];
            v.x = tf32r(v.x); v.y = tf32r(v.y); v.z = tf32r(v.z); v.w = tf32r(v.w);
            ((float4*)g_w2r)[q] = v;
        }
    }
}

// ================= TF32 GEMM, cp.async 3-stage: g_y = (A @ W) * dinv[row] =================
// CTA 160 x 256 (full N), 640 threads (20 warps, 5x4), warptile 32x64.
// CVTA: A is raw fp32 (layer 1) -> round A-fragments in-register (RNA, same grid as prep).
#define AST 36
#define BST 264
#define A_F (160 * AST)
#define B_F (32 * BST)
#define STG_F (A_F + B_F)
#define SMEM_GEMM_BYTES (3 * STG_F * 4)

template<int K, bool CVTA>
__global__ void __launch_bounds__(640, 1)
k_gemm_cp(const float* __restrict__ A, const float* __restrict__ W, int M)
{
    extern __shared__ float sm[];
    const uint32_t sbase = smem_u32(sm);

    const int tid = threadIdx.x;
    const int wid = tid >> 5;
    const int lid = tid & 31;
    const int gid = lid >> 2;
    const int tig = lid & 3;
    const int warpM = wid % 5;
    const int warpN = wid / 5;
    const int rowBase = blockIdx.x * 160;
    constexpr int NC = K / 32;

    float C[2][8][4];
    #pragma unroll
    for (int mt = 0; mt < 2; mt++)
        #pragma unroll
        for (int nt = 0; nt < 8; nt++)
            #pragma unroll
            for (int i = 0; i < 4; i++) C[mt][nt][i] = 0.f;

    auto stage = [&](int buf, int c) {
        uint32_t Asb = sbase + buf * (STG_F * 4);
        uint32_t Bsb = Asb + A_F * 4;
        #pragma unroll
        for (int i = 0; i < 2; i++) {
            int idx = tid + i * 640;
            int m = idx >> 3, k4 = (idx & 7) << 2;
            const float* s = A + (size_t)(rowBase + m) * K + c * 32 + k4;
            uint32_t d = Asb + (uint32_t)(m * AST + k4) * 4;
            int sz = (rowBase + m < M) ? 16 : 0;
            asm volatile("cp.async.cg.shared.global [%0], [%1], 16, %2;"
                         :: "r"(d), "l"(s), "r"(sz) : "memory");
        }
        #pragma unroll
        for (int i = 0; i < 4; i++) {
            int idx = tid + i * 640;
            if (idx < 2048) {
                int k = idx >> 6, n4 = (idx & 63) << 2;
                const float* s = W + (size_t)(c * 32 + k) * DH + n4;
                uint32_t d = Bsb + (uint32_t)(k * BST + n4) * 4;
                asm volatile("cp.async.cg.shared.global [%0], [%1], 16;"
                             :: "r"(d), "l"(s) : "memory");
            }
        }
    };

    stage(0, 0);
    asm volatile("cp.async.commit_group;" ::: "memory");
    if (NC > 1) {
        stage(1, 1);
        asm volatile("cp.async.commit_group;" ::: "memory");
    }

    for (int c = 0; c < NC; c++) {
        if (c + 1 < NC) asm volatile("cp.async.wait_group 1;" ::: "memory");
        else            asm volatile("cp.async.wait_group 0;" ::: "memory");
        __syncthreads();
        if (c + 2 < NC) {
            stage((c + 2) % 3, c + 2);
            asm volatile("cp.async.commit_group;" ::: "memory");
        }

        const float* As = sm + (c % 3) * STG_F;
        const float* Bs = As + A_F;

        #pragma unroll
        for (int ks = 0; ks < 4; ks++) {
            const int kk = ks * 8 + tig;
            uint32_t a[2][4];
            #pragma unroll
            for (int mt = 0; mt < 2; mt++) {
                int mr = warpM * 32 + mt * 16 + gid;
                if (CVTA) {
                    a[mt][0] = __float_as_uint(tf32r(As[mr * AST + kk]));
                    a[mt][1] = __float_as_uint(tf32r(As[(mr + 8) * AST + kk]));
                    a[mt][2] = __float_as_uint(tf32r(As[mr * AST + kk + 4]));
                    a[mt][3] = __float_as_uint(tf32r(As[(mr + 8) * AST + kk + 4]));
                } else {
                    a[mt][0] = __float_as_uint(As[mr * AST + kk]);
                    a[mt][1] = __float_as_uint(As[(mr + 8) * AST + kk]);
                    a[mt][2] = __float_as_uint(As[mr * AST + kk + 4]);
                    a[mt][3] = __float_as_uint(As[(mr + 8) * AST + kk + 4]);
                }
            }
            #pragma unroll
            for (int nt = 0; nt < 8; nt++) {
                int nc = warpN * 64 + nt * 8 + gid;
                uint32_t b[2];
                b[0] = __float_as_uint(Bs[kk * BST + nc]);
                b[1] = __float_as_uint(Bs[(kk + 4) * BST + nc]);
                mma_tf32(C[0][nt], a[0], b);
                mma_tf32(C[1][nt], a[1], b);
            }
        }
    }

    // epilogue: dinv = rsqrt(1 + indeg), scale, write g_y
    #pragma unroll
    for (int mt = 0; mt < 2; mt++) {
        int gr0 = rowBase + warpM * 32 + mt * 16 + gid;
        int gr1 = gr0 + 8;
        float d0 = (gr0 < M) ? rsqrtf(1.0f + (float)g_icnt[gr0]) : 0.f;
        float d1 = (gr1 < M) ? rsqrtf(1.0f + (float)g_icnt[gr1]) : 0.f;
        #pragma unroll
        for (int nt = 0; nt < 8; nt++) {
            int col = warpN * 64 + nt * 8 + tig * 2;
            if (gr0 < M) {
                float2 v = make_float2(C[mt][nt][0] * d0, C[mt][nt][1] * d0);
                *(float2*)&g_y[(size_t)gr0 * DH + col] = v;
            }
            if (gr1 < M) {
                float2 v = make_float2(C[mt][nt][2] * d1, C[mt][nt][3] * d1);
                *(float2*)&g_y[(size_t)gr1 * DH + col] = v;
            }
        }
    }
}

// ================= CSR gather: 64 threads/node, 8-deep load batches =================
// LAYER1: writes g_h (tf32-rounded), accumulates group counts.
// LAYER2: block-aggregated mean-pool (sorted batch -> smem tile), clears g_icnt.
template<bool LAYER2>
__global__ void __launch_bounds__(256)
k_gather(const int* __restrict__ batch, const float* __restrict__ bias, int N)
{
    __shared__ float sp[DH];
    __shared__ int sg;

    const int node = blockIdx.x * 4 + (threadIdx.x >> 6);
    const bool valid = node < N;
    const int c = (threadIdx.x & 63) << 2;

    if (LAYER2) {
        sp[threadIdx.x] = 0.f;
        if (threadIdx.x == 0) sg = batch[min(blockIdx.x * 4, N - 1)];
        __syncthreads();
    } else {
        if (!valid) return;
    }

    float acc[4] = {0.f, 0.f, 0.f, 0.f};
    int cnt0 = 0;

    if (valid) {
        cnt0 = g_icnt[node];
        const int cnt = min(cnt0, CAP);
        if (!LAYER2 && (threadIdx.x & 63) == 0)
            atomicAdd(&g_cnt[batch[node]], 1.0f);

        addf4(acc, *(const float4*)(g_y + (size_t)node * DH + c));   // self loop

        const int4* ip = (const int4*)(g_eslot + node * CAP);        // CAP%4==0
        int j = 0;
        for (; j + 8 <= cnt; j += 8) {
            int4 sA = ip[j >> 2];
            int4 sB = ip[(j >> 2) + 1];
            float4 v0 = *(const float4*)(g_y + (size_t)sA.x * DH + c);
            float4 v1 = *(const float4*)(g_y + (size_t)sA.y * DH + c);
            float4 v2 = *(const float4*)(g_y + (size_t)sA.z * DH + c);
            float4 v3 = *(const float4*)(g_y + (size_t)sA.w * DH + c);
            float4 v4 = *(const float4*)(g_y + (size_t)sB.x * DH + c);
            float4 v5 = *(const float4*)(g_y + (size_t)sB.y * DH + c);
            float4 v6 = *(const float4*)(g_y + (size_t)sB.z * DH + c);
            float4 v7 = *(const float4*)(g_y + (size_t)sB.w * DH + c);
            addf4(acc, v0); addf4(acc, v1); addf4(acc, v2); addf4(acc, v3);
            addf4(acc, v4); addf4(acc, v5); addf4(acc, v6); addf4(acc, v7);
        }
        if (j + 4 <= cnt) {
            int4 sA = ip[j >> 2];
            float4 v0 = *(const float4*)(g_y + (size_t)sA.x * DH + c);
            float4 v1 = *(const float4*)(g_y + (size_t)sA.y * DH + c);
            float4 v2 = *(const float4*)(g_y + (size_t)sA.z * DH + c);
            float4 v3 = *(const float4*)(g_y + (size_t)sA.w * DH + c);
            addf4(acc, v0); addf4(acc, v1); addf4(acc, v2); addf4(acc, v3);
            j += 4;
        }
        for (; j < cnt; j++) {
            int s = g_eslot[node * CAP + j];
            addf4(acc, *(const float4*)(g_y + (size_t)s * DH + c));
        }
    }

    if (!LAYER2) {
        const float dv = rsqrtf(1.0f + (float)cnt0);
        float4 b = *(const float4*)(bias + c);
        float4 r;
        r.x = tf32r(fmaxf(fmaf(acc[0], dv, b.x), 0.f));   // pre-round for GEMM2
        r.y = tf32r(fmaxf(fmaf(acc[1], dv, b.y), 0.f));
        r.z = tf32r(fmaxf(fmaf(acc[2], dv, b.z), 0.f));
        r.w = tf32r(fmaxf(fmaf(acc[3], dv, b.w), 0.f));
        *(float4*)(g_h + (size_t)node * DH + c) = r;
    } else {
        if (valid) {
            const float dv = rsqrtf(1.0f + (float)cnt0);
            float4 b = *(const float4*)(bias + c);
            float r[4];
            r[0] = fmaxf(fmaf(acc[0], dv, b.x), 0.f);
            r[1] = fmaxf(fmaf(acc[1], dv, b.y), 0.f);
            r[2] = fmaxf(fmaf(acc[2], dv, b.z), 0.f);
            r[3] = fmaxf(fmaf(acc[3], dv, b.w), 0.f);
            int g = batch[node];
            if (g == sg) {
                #pragma unroll
                for (int i = 0; i < 4; i++) atomicAdd(&sp[c + i], r[i]);
            } else {
                #pragma unroll
                for (int i = 0; i < 4; i++) atomicAdd(&g_pool[(size_t)g * DH + c + i], r[i]);
            }
            if ((threadIdx.x & 63) == 0) g_icnt[node] = 0;   // self-clean for next launch
        }
        __syncthreads();
        atomicAdd(&g_pool[(size_t)sg * DH + threadIdx.x], sp[threadIdx.x]);
    }
}

// ================= final FC (+ scratch clear) =================
__global__ void k_fc(const float* __restrict__ wfc, const float* __restrict__ bfc,
                     float* __restrict__ out)
{
    int w = (blockIdx.x * blockDim.x + threadIdx.x) >> 5;
    int lane = threadIdx.x & 31;
    if (w >= GNUM) return;
    float sum = 0.f;
    #pragma unroll
    for (int j = lane; j < DH; j += 32) {
        sum += g_pool[w * DH + j] * wfc[j];
        g_pool[w * DH + j] = 0.f;          // self-clean
    }
    #pragma unroll
    for (int o = 16; o; o >>= 1)
        sum += __shfl_xor_sync(0xffffffffu, sum, o);
    if (lane == 0) {
        float cntw = g_cnt[w];
        g_cnt[w] = 0.f;                    // self-clean
        out[w] = sum / fmaxf(cntw, 1.f) + bfc[0];
    }
}

// ================= launch =================
extern "C" void kernel_launch(void* const* d_in, const int* in_sizes, int n_in,
                              void* d_out, int out_size)
{
    const float* x     = (const float*)d_in[0];
    const int*   ei    = (const int*)  d_in[1];
    const int*   batch = (const int*)  d_in[2];
    const float* W1    = (const float*)d_in[3];
    const float* b1    = (const float*)d_in[4];
    const float* W2    = (const float*)d_in[5];
    const float* b2    = (const float*)d_in[6];
    const float* wfc   = (const float*)d_in[7];
    const float* bfc   = (const float*)d_in[8];
    float* out = (float*)d_out;

    const int N = in_sizes[2];        // 20000
    const int E = in_sizes[1] / 2;    // 320000
    const int* src = ei;
    const int* dst = ei + E;

    cudaFuncSetAttribute(k_gemm_cp<DIN, true>,
                         cudaFuncAttributeMaxDynamicSharedMemorySize, SMEM_GEMM_BYTES);
    cudaFuncSetAttribute(k_gemm_cp<DH, false>,
                         cudaFuncAttributeMaxDynamicSharedMemorySize, SMEM_GEMM_BYTES);

    // fused prep: CSR fill + tf32-round W1, W2 (x no longer copied)
    const int FILL_B = (E + 255) / 256;
    const int W1_B   = (DIN * DH / 4) / 256;
    const int W2_B   = (DH * DH / 4) / 256;
    k_prep<<<FILL_B + W1_B + W2_B, 256>>>(src, dst, W1, W2, E);

    float* w1r; cudaGetSymbolAddress((void**)&w1r, g_w1r);
    float* w2r; cudaGetSymbolAddress((void**)&w2r, g_w2r);
    float* h;   cudaGetSymbolAddress((void**)&h, g_h);

    const int gemm_blocks = (N + 159) / 160;   // 125
    const int gat_blocks  = (N + 3) / 4;

    // layer 1 (A = raw x, rounded in-register)
    k_gemm_cp<DIN, true><<<gemm_blocks, 640, SMEM_GEMM_BYTES>>>(x, w1r, N);
    k_gather<false><<<gat_blocks, 256>>>(batch, b1, N);

    // layer 2 (A = g_h, already on tf32 grid)
    k_gemm_cp<DH, false><<<gemm_blocks, 640, SMEM_GEMM_BYTES>>>(h, w2r, N);
    k_gather<true><<<gat_blocks, 256>>>(batch, b2, N);

    // fc (also clears pool/cnt for next launch)
    k_fc<<<GNUM * 32 / 128, 128>>>(wfc, bfc, out);
}

// round 14
// speedup vs baseline: 1.6138x; 1.1577x over previous
#include <cuda_runtime.h>
#include <cuda_fp16.h>
#include <cstdint>

#define DIN 512
#define DH  256
#define GNUM 128
#define NMAX 20000
#define EMAX 320000
#define CAP  96          // padded-CSR slots per node

// ---- scratch (static __device__ globals; zero-initialized at load) ----
__device__ float  g_y[NMAX * DH];       // messages y = (A@W)*dinv[row] (fp32)
__device__ __half g_x16[NMAX * DIN];    // x converted to fp16
__device__ __half g_h16[NMAX * DH];     // layer-1 output, fp16 (GEMM-2 input)
__device__ __half g_w1t[DH * DIN];      // W1^T fp16: [256][512]
__device__ __half g_w2t[DH * DH];       // W2^T fp16: [256][256]
__device__ int    g_icnt[NMAX];         // in-degree (excl. self); cleared by gather<1>
__device__ int    g_eslot[NMAX * CAP];  // padded CSR: src per incoming edge
__device__ float  g_pool[GNUM * DH];    // cleared by k_fc after read
__device__ float  g_cnt[GNUM];          // cleared by k_fc after read

// ================= helpers =================
__device__ __forceinline__ uint32_t smem_u32(const void* p) {
    uint32_t a;
    asm("{ .reg .u64 t; cvta.to.shared.u64 t, %1; cvt.u32.u64 %0, t; }" : "=r"(a) : "l"(p));
    return a;
}

__device__ __forceinline__ void mma_f16(float* c, const uint32_t* a, const uint32_t* b) {
    asm volatile("mma.sync.aligned.m16n8k16.row.col.f32.f16.f16.f32 "
        "{%0,%1,%2,%3}, {%4,%5,%6,%7}, {%8,%9}, {%0,%1,%2,%3};"
        : "+f"(c[0]), "+f"(c[1]), "+f"(c[2]), "+f"(c[3])
        : "r"(a[0]), "r"(a[1]), "r"(a[2]), "r"(a[3]), "r"(b[0]), "r"(b[1]));
}

__device__ __forceinline__ void addf4(float* a, float4 v) {
    a[0] += v.x; a[1] += v.y; a[2] += v.z; a[3] += v.w;
}

// ================= fused prep: CSR fill + x->fp16 + W1/W2 transpose->fp16 =================
__global__ void k_prep(const int* __restrict__ src, const int* __restrict__ dst,
                       const float* __restrict__ x, const float* __restrict__ W1,
                       const float* __restrict__ W2, int E, int N)
{
    const int FILL_B = (E + 255) / 256;
    const int XQ     = N * DIN / 4;                 // float4 quads
    const int X16_B  = (XQ + 255) / 256;
    const int W1T_B  = (DIN / 32) * (DH / 32);      // 128 tiles
    const int b = blockIdx.x;
    const int tid = threadIdx.x;

    if (b < FILL_B) {
        int e = b * 256 + tid;
        if (e < E) {
            int d = dst[e];
            int pos = atomicAdd(&g_icnt[d], 1);
            if (pos < CAP) g_eslot[d * CAP + pos] = src[e];
        }
    } else if (b < FILL_B + X16_B) {
        int q = (b - FILL_B) * 256 + tid;
        if (q < XQ) {
            float4 v = ((const float4*)x)[q];
            __half2 h01 = __floats2half2_rn(v.x, v.y);
            __half2 h23 = __floats2half2_rn(v.z, v.w);
            uint2 u = make_uint2(*(uint32_t*)&h01, *(uint32_t*)&h23);
            ((uint2*)g_x16)[q] = u;
        }
    } else {
        // tiled transpose W[k][n] -> WT16[n][k], fp16
        __shared__ float tile[32][33];
        const float* W;  __half* WT;  int K, tiles_k;
        int t = b - FILL_B - X16_B;
        if (t < W1T_B) { W = W1; WT = g_w1t; K = DIN; tiles_k = DIN / 32; }
        else           { W = W2; WT = g_w2t; K = DH;  tiles_k = DH / 32; t -= W1T_B; }
        int kb = (t % tiles_k) * 32, nb = (t / tiles_k) * 32;
        int r0 = tid >> 5, c = tid & 31;
        #pragma unroll
        for (int i = 0; i < 4; i++) {
            int row = r0 + i * 8;
            tile[row][c] = W[(size_t)(kb + row) * DH + nb + c];
        }
        __syncthreads();
        #pragma unroll
        for (int i = 0; i < 4; i++) {
            int row = r0 + i * 8;
            WT[(size_t)(nb + row) * K + kb + c] = __float2half_rn(tile[c][row]);
        }
    }
}

// ================= FP16 GEMM, cp.async 3-stage: g_y = (A @ W) * dinv[row] =================
// CTA 160 x 256 (full N), 640 threads (20 warps, 5x4), warptile 32x64, mma m16n8k16.
// A fp16 [M][K]; W fp16 TRANSPOSED [256][K]. K-chunk 64, smem stride 72 halves (144B).
#define KC 64
#define HST 72                       // halves per smem row (64 + 8 pad)
#define A_H (160 * HST)              // 11520 halves = 23040 B
#define B_H (256 * HST)              // 18432 halves = 36864 B
#define STG_B ((A_H + B_H) * 2)      // 59904 B per stage
#define SMEM_GEMM_BYTES (3 * STG_B)  // 179712 B

template<int K>
__global__ void __launch_bounds__(640, 1)
k_gemm_h(const __half* __restrict__ A, const __half* __restrict__ WT, int M)
{
    extern __shared__ __half smh[];
    const uint32_t sbase = smem_u32(smh);

    const int tid = threadIdx.x;
    const int wid = tid >> 5;
    const int lid = tid & 31;
    const int gid = lid >> 2;
    const int tig = lid & 3;
    const int warpM = wid % 5;
    const int warpN = wid / 5;
    const int rowBase = blockIdx.x * 160;
    constexpr int NC = K / KC;

    float C[2][8][4];
    #pragma unroll
    for (int mt = 0; mt < 2; mt++)
        #pragma unroll
        for (int nt = 0; nt < 8; nt++)
            #pragma unroll
            for (int i = 0; i < 4; i++) C[mt][nt][i] = 0.f;

    auto stage = [&](int buf, int c) {
        uint32_t Asb = sbase + buf * STG_B;
        uint32_t Bsb = Asb + A_H * 2;
        // A chunk: 160 rows x 64 halves = 1280 x 16B
        #pragma unroll
        for (int i = 0; i < 2; i++) {
            int idx = tid + i * 640;
            int m = idx >> 3, seg = idx & 7;
            const __half* s = A + (size_t)(rowBase + m) * K + c * KC + seg * 8;
            uint32_t d = Asb + (uint32_t)(m * 144 + seg * 16);
            int sz = (rowBase + m < M) ? 16 : 0;
            asm volatile("cp.async.cg.shared.global [%0], [%1], 16, %2;"
                         :: "r"(d), "l"(s), "r"(sz) : "memory");
        }
        // B chunk: 256 rows (n) x 64 halves = 2048 x 16B
        #pragma unroll
        for (int i = 0; i < 4; i++) {
            int idx = tid + i * 640;
            if (idx < 2048) {
                int n = idx >> 3, seg = idx & 7;
                const __half* s = WT + (size_t)n * K + c * KC + seg * 8;
                uint32_t d = Bsb + (uint32_t)(n * 144 + seg * 16);
                asm volatile("cp.async.cg.shared.global [%0], [%1], 16;"
                             :: "r"(d), "l"(s) : "memory");
            }
        }
    };

    stage(0, 0);
    asm volatile("cp.async.commit_group;" ::: "memory");
    if (NC > 1) {
        stage(1, 1);
        asm volatile("cp.async.commit_group;" ::: "memory");
    }

    for (int c = 0; c < NC; c++) {
        if (c + 1 < NC) asm volatile("cp.async.wait_group 1;" ::: "memory");
        else            asm volatile("cp.async.wait_group 0;" ::: "memory");
        __syncthreads();
        if (c + 2 < NC) {
            stage((c + 2) % 3, c + 2);
            asm volatile("cp.async.commit_group;" ::: "memory");
        }

        const __half* As = smh + (c % 3) * (STG_B / 2);
        const __half* Bs = As + A_H;

        #pragma unroll
        for (int ks = 0; ks < 4; ks++) {            // 4 x k16
            const int kk = ks * 16 + 2 * tig;
            uint32_t a[2][4];
            #pragma unroll
            for (int mt = 0; mt < 2; mt++) {
                int m0 = warpM * 32 + mt * 16 + gid;
                const __half* p0 = As + m0 * HST + kk;
                const __half* p1 = p0 + 8 * HST;
                a[mt][0] = *(const uint32_t*)p0;        // (row gid,   k..k+1)
                a[mt][1] = *(const uint32_t*)p1;        // (row gid+8, k..k+1)
                a[mt][2] = *(const uint32_t*)(p0 + 8);  // (row gid,   k+8..k+9)
                a[mt][3] = *(const uint32_t*)(p1 + 8);  // (row gid+8, k+8..k+9)
            }
            #pragma unroll
            for (int nt = 0; nt < 8; nt++) {
                int n = warpN * 64 + nt * 8 + gid;
                const __half* q = Bs + n * HST + kk;
                uint32_t b[2];
                b[0] = *(const uint32_t*)q;             // (k..k+1,   col n)
                b[1] = *(const uint32_t*)(q + 8);       // (k+8..k+9, col n)
                mma_f16(C[0][nt], a[0], b);
                mma_f16(C[1][nt], a[1], b);
            }
        }
    }

    // epilogue: dinv = rsqrt(1 + indeg), scale, write g_y (fp32, float2 pairs)
    #pragma unroll
    for (int mt = 0; mt < 2; mt++) {
        int gr0 = rowBase + warpM * 32 + mt * 16 + gid;
        int gr1 = gr0 + 8;
        float d0 = (gr0 < M) ? rsqrtf(1.0f + (float)g_icnt[gr0]) : 0.f;
        float d1 = (gr1 < M) ? rsqrtf(1.0f + (float)g_icnt[gr1]) : 0.f;
        #pragma unroll
        for (int nt = 0; nt < 8; nt++) {
            int col = warpN * 64 + nt * 8 + tig * 2;
            if (gr0 < M) {
                float2 v = make_float2(C[mt][nt][0] * d0, C[mt][nt][1] * d0);
                *(float2*)&g_y[(size_t)gr0 * DH + col] = v;
            }
            if (gr1 < M) {
                float2 v = make_float2(C[mt][nt][2] * d1, C[mt][nt][3] * d1);
                *(float2*)&g_y[(size_t)gr1 * DH + col] = v;
            }
        }
    }
}

// ================= CSR gather: 64 threads/node, 8-deep load batches =================
// LAYER1: writes g_h16 (fp16, GEMM2 input), accumulates group counts.
// LAYER2: block-aggregated mean-pool (sorted batch -> smem tile), clears g_icnt.
template<bool LAYER2>
__global__ void __launch_bounds__(256)
k_gather(const int* __restrict__ batch, const float* __restrict__ bias, int N)
{
    __shared__ float sp[DH];
    __shared__ int sg;

    const int node = blockIdx.x * 4 + (threadIdx.x >> 6);
    const bool valid = node < N;
    const int c = (threadIdx.x & 63) << 2;

    if (LAYER2) {
        sp[threadIdx.x] = 0.f;
        if (threadIdx.x == 0) sg = batch[min(blockIdx.x * 4, N - 1)];
        __syncthreads();
    } else {
        if (!valid) return;
    }

    float acc[4] = {0.f, 0.f, 0.f, 0.f};
    int cnt0 = 0;

    if (valid) {
        cnt0 = g_icnt[node];
        const int cnt = min(cnt0, CAP);
        if (!LAYER2 && (threadIdx.x & 63) == 0)
            atomicAdd(&g_cnt[batch[node]], 1.0f);

        addf4(acc, *(const float4*)(g_y + (size_t)node * DH + c));   // self loop

        const int4* ip = (const int4*)(g_eslot + node * CAP);        // CAP%4==0
        int j = 0;
        for (; j + 8 <= cnt; j += 8) {
            int4 sA = ip[j >> 2];
            int4 sB = ip[(j >> 2) + 1];
            float4 v0 = *(const float4*)(g_y + (size_t)sA.x * DH + c);
            float4 v1 = *(const float4*)(g_y + (size_t)sA.y * DH + c);
            float4 v2 = *(const float4*)(g_y + (size_t)sA.z * DH + c);
            float4 v3 = *(const float4*)(g_y + (size_t)sA.w * DH + c);
            float4 v4 = *(const float4*)(g_y + (size_t)sB.x * DH + c);
            float4 v5 = *(const float4*)(g_y + (size_t)sB.y * DH + c);
            float4 v6 = *(const float4*)(g_y + (size_t)sB.z * DH + c);
            float4 v7 = *(const float4*)(g_y + (size_t)sB.w * DH + c);
            addf4(acc, v0); addf4(acc, v1); addf4(acc, v2); addf4(acc, v3);
            addf4(acc, v4); addf4(acc, v5); addf4(acc, v6); addf4(acc, v7);
        }
        if (j + 4 <= cnt) {
            int4 sA = ip[j >> 2];
            float4 v0 = *(const float4*)(g_y + (size_t)sA.x * DH + c);
            float4 v1 = *(const float4*)(g_y + (size_t)sA.y * DH + c);
            float4 v2 = *(const float4*)(g_y + (size_t)sA.z * DH + c);
            float4 v3 = *(const float4*)(g_y + (size_t)sA.w * DH + c);
            addf4(acc, v0); addf4(acc, v1); addf4(acc, v2); addf4(acc, v3);
            j += 4;
        }
        for (; j < cnt; j++) {
            int s = g_eslot[node * CAP + j];
            addf4(acc, *(const float4*)(g_y + (size_t)s * DH + c));
        }
    }

    if (!LAYER2) {
        const float dv = rsqrtf(1.0f + (float)cnt0);
        float4 b = *(const float4*)(bias + c);
        __half2 h01 = __floats2half2_rn(fmaxf(fmaf(acc[0], dv, b.x), 0.f),
                                        fmaxf(fmaf(acc[1], dv, b.y), 0.f));
        __half2 h23 = __floats2half2_rn(fmaxf(fmaf(acc[2], dv, b.z), 0.f),
                                        fmaxf(fmaf(acc[3], dv, b.w), 0.f));
        uint2 u = make_uint2(*(uint32_t*)&h01, *(uint32_t*)&h23);
        *(uint2*)(g_h16 + (size_t)node * DH + c) = u;
    } else {
        if (valid) {
            const float dv = rsqrtf(1.0f + (float)cnt0);
            float4 b = *(const float4*)(bias + c);
            float r[4];
            r[0] = fmaxf(fmaf(acc[0], dv, b.x), 0.f);
            r[1] = fmaxf(fmaf(acc[1], dv, b.y), 0.f);
            r[2] = fmaxf(fmaf(acc[2], dv, b.z), 0.f);
            r[3] = fmaxf(fmaf(acc[3], dv, b.w), 0.f);
            int g = batch[node];
            if (g == sg) {
                #pragma unroll
                for (int i = 0; i < 4; i++) atomicAdd(&sp[c + i], r[i]);
            } else {
                #pragma unroll
                for (int i = 0; i < 4; i++) atomicAdd(&g_pool[(size_t)g * DH + c + i], r[i]);
            }
            if ((threadIdx.x & 63) == 0) g_icnt[node] = 0;   // self-clean for next launch
        }
        __syncthreads();
        atomicAdd(&g_pool[(size_t)sg * DH + threadIdx.x], sp[threadIdx.x]);
    }
}

// ================= final FC (+ scratch clear) =================
__global__ void k_fc(const float* __restrict__ wfc, const float* __restrict__ bfc,
                     float* __restrict__ out)
{
    int w = (blockIdx.x * blockDim.x + threadIdx.x) >> 5;
    int lane = threadIdx.x & 31;
    if (w >= GNUM) return;
    float sum = 0.f;
    #pragma unroll
    for (int j = lane; j < DH; j += 32) {
        sum += g_pool[w * DH + j] * wfc[j];
        g_pool[w * DH + j] = 0.f;          // self-clean
    }
    #pragma unroll
    for (int o = 16; o; o >>= 1)
        sum += __shfl_xor_sync(0xffffffffu, sum, o);
    if (lane == 0) {
        float cntw = g_cnt[w];
        g_cnt[w] = 0.f;                    // self-clean
        out[w] = sum / fmaxf(cntw, 1.f) + bfc[0];
    }
}

// ================= launch =================
extern "C" void kernel_launch(void* const* d_in, const int* in_sizes, int n_in,
                              void* d_out, int out_size)
{
    const float* x     = (const float*)d_in[0];
    const int*   ei    = (const int*)  d_in[1];
    const int*   batch = (const int*)  d_in[2];
    const float* W1    = (const float*)d_in[3];
    const float* b1    = (const float*)d_in[4];
    const float* W2    = (const float*)d_in[5];
    const float* b2    = (const float*)d_in[6];
    const float* wfc   = (const float*)d_in[7];
    const float* bfc   = (const float*)d_in[8];
    float* out = (float*)d_out;

    const int N = in_sizes[2];        // 20000
    const int E = in_sizes[1] / 2;    // 320000
    const int* src = ei;
    const int* dst = ei + E;

    cudaFuncSetAttribute(k_gemm_h<DIN>,
                         cudaFuncAttributeMaxDynamicSharedMemorySize, SMEM_GEMM_BYTES);
    cudaFuncSetAttribute(k_gemm_h<DH>,
                         cudaFuncAttributeMaxDynamicSharedMemorySize, SMEM_GEMM_BYTES);

    // fused prep: CSR fill + x->fp16 + W1/W2 transpose->fp16
    const int FILL_B = (E + 255) / 256;
    const int X16_B  = (N * DIN / 4 + 255) / 256;
    const int W1T_B  = (DIN / 32) * (DH / 32);
    const int W2T_B  = (DH / 32) * (DH / 32);
    k_prep<<<FILL_B + X16_B + W1T_B + W2T_B, 256>>>(src, dst, x, W1, W2, E, N);

    __half* x16; cudaGetSymbolAddress((void**)&x16, g_x16);
    __half* w1t; cudaGetSymbolAddress((void**)&w1t, g_w1t);
    __half* w2t; cudaGetSymbolAddress((void**)&w2t, g_w2t);
    __half* h16; cudaGetSymbolAddress((void**)&h16, g_h16);

    const int gemm_blocks = (N + 159) / 160;   // 125
    const int gat_blocks  = (N + 3) / 4;

    // layer 1
    k_gemm_h<DIN><<<gemm_blocks, 640, SMEM_GEMM_BYTES>>>(x16, w1t, N);
    k_gather<false><<<gat_blocks, 256>>>(batch, b1, N);

    // layer 2
    k_gemm_h<DH><<<gemm_blocks, 640, SMEM_GEMM_BYTES>>>(h16, w2t, N);
    k_gather<true><<<gat_blocks, 256>>>(batch, b2, N);

    // fc (also clears pool/cnt for next launch)
    k_fc<<<GNUM * 32 / 128, 128>>>(wfc, bfc, out);
}

// round 16
// speedup vs baseline: 1.6467x; 1.0204x over previous
#include <cuda_runtime.h>
#include <cuda_fp16.h>
#include <cstdint>

#define DIN 512
#define DH  256
#define GNUM 128
#define NMAX 20000
#define EMAX 320000
#define CAP  96          // padded-CSR slots per node

// ---- scratch (static __device__ globals; zero-initialized at load) ----
__device__ float  g_y[NMAX * DH];       // messages y = (A@W)*dinv[row] (fp32)
__device__ __half g_x16[NMAX * DIN];    // x converted to fp16
__device__ __half g_h16[NMAX * DH];     // layer-1 output, fp16 (GEMM-2 input)
__device__ __half g_w1t[DH * DIN];      // W1^T fp16: [256][512]
__device__ __half g_w2t[DH * DH];       // W2^T fp16: [256][256]
__device__ int    g_icnt[NMAX];         // in-degree (excl. self); cleared by gather<1>
__device__ int    g_eslot[NMAX * CAP];  // padded CSR: src per incoming edge
__device__ float  g_pool[GNUM * DH];    // cleared by k_fc after read
__device__ float  g_cnt[GNUM];          // cleared by k_fc after read

// ================= helpers =================
__device__ __forceinline__ uint32_t smem_u32(const void* p) {
    uint32_t a;
    asm("{ .reg .u64 t; cvta.to.shared.u64 t, %1; cvt.u32.u64 %0, t; }" : "=r"(a) : "l"(p));
    return a;
}

__device__ __forceinline__ void mma_f16(float* c, const uint32_t* a, const uint32_t* b) {
    asm volatile("mma.sync.aligned.m16n8k16.row.col.f32.f16.f16.f32 "
        "{%0,%1,%2,%3}, {%4,%5,%6,%7}, {%8,%9}, {%0,%1,%2,%3};"
        : "+f"(c[0]), "+f"(c[1]), "+f"(c[2]), "+f"(c[3])
        : "r"(a[0]), "r"(a[1]), "r"(a[2]), "r"(a[3]), "r"(b[0]), "r"(b[1]));
}

#define LDSM_X4(r0, r1, r2, r3, addr) \
    asm volatile("ldmatrix.sync.aligned.m8n8.x4.shared.b16 {%0,%1,%2,%3}, [%4];" \
        : "=r"(r0), "=r"(r1), "=r"(r2), "=r"(r3) : "r"(addr))

__device__ __forceinline__ void addf4(float* a, float4 v) {
    a[0] += v.x; a[1] += v.y; a[2] += v.z; a[3] += v.w;
}

// ================= fused prep: CSR fill + x->fp16 + W1/W2 transpose->fp16 =================
__global__ void k_prep(const int* __restrict__ src, const int* __restrict__ dst,
                       const float* __restrict__ x, const float* __restrict__ W1,
                       const float* __restrict__ W2, int E, int N)
{
    const int FILL_B = (E + 255) / 256;
    const int XQ     = N * DIN / 4;
    const int X16_B  = (XQ + 255) / 256;
    const int W1T_B  = (DIN / 32) * (DH / 32);
    const int b = blockIdx.x;
    const int tid = threadIdx.x;

    if (b < FILL_B) {
        int e = b * 256 + tid;
        if (e < E) {
            int d = dst[e];
            int pos = atomicAdd(&g_icnt[d], 1);
            if (pos < CAP) g_eslot[d * CAP + pos] = src[e];
        }
    } else if (b < FILL_B + X16_B) {
        int q = (b - FILL_B) * 256 + tid;
        if (q < XQ) {
            float4 v = ((const float4*)x)[q];
            __half2 h01 = __floats2half2_rn(v.x, v.y);
            __half2 h23 = __floats2half2_rn(v.z, v.w);
            uint2 u = make_uint2(*(uint32_t*)&h01, *(uint32_t*)&h23);
            ((uint2*)g_x16)[q] = u;
        }
    } else {
        __shared__ float tile[32][33];
        const float* W;  __half* WT;  int K, tiles_k;
        int t = b - FILL_B - X16_B;
        if (t < W1T_B) { W = W1; WT = g_w1t; K = DIN; tiles_k = DIN / 32; }
        else           { W = W2; WT = g_w2t; K = DH;  tiles_k = DH / 32; t -= W1T_B; }
        int kb = (t % tiles_k) * 32, nb = (t / tiles_k) * 32;
        int r0 = tid >> 5, c = tid & 31;
        #pragma unroll
        for (int i = 0; i < 4; i++) {
            int row = r0 + i * 8;
            tile[row][c] = W[(size_t)(kb + row) * DH + nb + c];
        }
        __syncthreads();
        #pragma unroll
        for (int i = 0; i < 4; i++) {
            int row = r0 + i * 8;
            WT[(size_t)(nb + row) * K + kb + c] = __float2half_rn(tile[c][row]);
        }
    }
}

// ================= FP16 GEMM, cp.async 3-stage + ldmatrix: g_y = (A @ W) * dinv[row] =================
// CTA 160 x 256, 640 threads (20 warps, 5x4), warptile 32x64, mma m16n8k16.
// A fp16 [M][K]; W fp16 transposed [256][K]. K-chunk 64, smem row stride 144 B.
#define KC 64
#define HST 72                       // halves per smem row (64 + 8 pad), 144 B
#define A_H (160 * HST)
#define B_H (256 * HST)
#define STG_B ((A_H + B_H) * 2)      // 59904 B per stage
#define SMEM_GEMM_BYTES (3 * STG_B)  // 179712 B

template<int K>
__global__ void __launch_bounds__(640, 1)
k_gemm_h(const __half* __restrict__ A, const __half* __restrict__ WT, int M)
{
    extern __shared__ __half smh[];
    const uint32_t sbase = smem_u32(smh);

    const int tid = threadIdx.x;
    const int wid = tid >> 5;
    const int lid = tid & 31;
    const int gid = lid >> 2;
    const int tig = lid & 3;
    const int warpM = wid % 5;
    const int warpN = wid / 5;
    const int rowBase = blockIdx.x * 160;
    constexpr int NC = K / KC;

    // ldmatrix per-lane byte offsets (within a stage buffer)
    // A (x4, per mt): rows = m0 + lid%16, koff16 = (lid/16)*16 bytes
    const uint32_t a_off0 = (uint32_t)((warpM * 32 + (lid & 15)) * 144 + (lid >> 4) * 16);
    const uint32_t a_off1 = a_off0 + 16u * 144u;
    // B (x4, per nt-pair): rows = nbase + (lid/16)*8 + lid%8, koff16 = ((lid%16)/8)*16
    const uint32_t b_offp = (uint32_t)((warpN * 64 + (lid >> 4) * 8 + (lid & 7)) * 144
                                       + (((lid >> 3) & 1) * 16));

    float C[2][8][4];
    #pragma unroll
    for (int mt = 0; mt < 2; mt++)
        #pragma unroll
        for (int nt = 0; nt < 8; nt++)
            #pragma unroll
            for (int i = 0; i < 4; i++) C[mt][nt][i] = 0.f;

    auto stage = [&](int buf, int c) {
        uint32_t Asb = sbase + buf * STG_B;
        uint32_t Bsb = Asb + A_H * 2;
        #pragma unroll
        for (int i = 0; i < 2; i++) {
            int idx = tid + i * 640;
            int m = idx >> 3, seg = idx & 7;
            const __half* s = A + (size_t)(rowBase + m) * K + c * KC + seg * 8;
            uint32_t d = Asb + (uint32_t)(m * 144 + seg * 16);
            int sz = (rowBase + m < M) ? 16 : 0;
            asm volatile("cp.async.cg.shared.global [%0], [%1], 16, %2;"
                         :: "r"(d), "l"(s), "r"(sz) : "memory");
        }
        #pragma unroll
        for (int i = 0; i < 4; i++) {
            int idx = tid + i * 640;
            if (idx < 2048) {
                int n = idx >> 3, seg = idx & 7;
                const __half* s = WT + (size_t)n * K + c * KC + seg * 8;
                uint32_t d = Bsb + (uint32_t)(n * 144 + seg * 16);
                asm volatile("cp.async.cg.shared.global [%0], [%1], 16;"
                             :: "r"(d), "l"(s) : "memory");
            }
        }
    };

    stage(0, 0);
    asm volatile("cp.async.commit_group;" ::: "memory");
    if (NC > 1) {
        stage(1, 1);
        asm volatile("cp.async.commit_group;" ::: "memory");
    }

    for (int c = 0; c < NC; c++) {
        if (c + 1 < NC) asm volatile("cp.async.wait_group 1;" ::: "memory");
        else            asm volatile("cp.async.wait_group 0;" ::: "memory");
        __syncthreads();
        if (c + 2 < NC) {
            stage((c + 2) % 3, c + 2);
            asm volatile("cp.async.commit_group;" ::: "memory");
        }

        const uint32_t Asu = sbase + (c % 3) * STG_B;
        const uint32_t Bsu = Asu + A_H * 2;

        #pragma unroll
        for (int ks = 0; ks < 4; ks++) {            // 4 x k16
            const uint32_t kso = (uint32_t)(ks * 32);
            uint32_t a[2][4];
            LDSM_X4(a[0][0], a[0][1], a[0][2], a[0][3], Asu + a_off0 + kso);
            LDSM_X4(a[1][0], a[1][1], a[1][2], a[1][3], Asu + a_off1 + kso);
            uint32_t bf[4][4];
            #pragma unroll
            for (int np = 0; np < 4; np++) {
                LDSM_X4(bf[np][0], bf[np][1], bf[np][2], bf[np][3],
                        Bsu + b_offp + (uint32_t)(np * 16 * 144) + kso);
            }
            #pragma unroll
            for (int nt = 0; nt < 8; nt++) {
                const uint32_t* b = &bf[nt >> 1][(nt & 1) * 2];
                mma_f16(C[0][nt], a[0], b);
                mma_f16(C[1][nt], a[1], b);
            }
        }
    }

    // epilogue: dinv = rsqrt(1 + indeg), scale, write g_y (fp32, float2 pairs)
    #pragma unroll
    for (int mt = 0; mt < 2; mt++) {
        int gr0 = rowBase + warpM * 32 + mt * 16 + gid;
        int gr1 = gr0 + 8;
        float d0 = (gr0 < M) ? rsqrtf(1.0f + (float)g_icnt[gr0]) : 0.f;
        float d1 = (gr1 < M) ? rsqrtf(1.0f + (float)g_icnt[gr1]) : 0.f;
        #pragma unroll
        for (int nt = 0; nt < 8; nt++) {
            int col = warpN * 64 + nt * 8 + tig * 2;
            if (gr0 < M) {
                float2 v = make_float2(C[mt][nt][0] * d0, C[mt][nt][1] * d0);
                *(float2*)&g_y[(size_t)gr0 * DH + col] = v;
            }
            if (gr1 < M) {
                float2 v = make_float2(C[mt][nt][2] * d1, C[mt][nt][3] * d1);
                *(float2*)&g_y[(size_t)gr1 * DH + col] = v;
            }
        }
    }
}

// ================= CSR gather: 64 threads/node, 8-deep load batches =================
template<bool LAYER2>
__global__ void __launch_bounds__(256)
k_gather(const int* __restrict__ batch, const float* __restrict__ bias, int N)
{
    __shared__ float sp[DH];
    __shared__ int sg;

    const int node = blockIdx.x * 4 + (threadIdx.x >> 6);
    const bool valid = node < N;
    const int c = (threadIdx.x & 63) << 2;

    if (LAYER2) {
        sp[threadIdx.x] = 0.f;
        if (threadIdx.x == 0) sg = batch[min(blockIdx.x * 4, N - 1)];
        __syncthreads();
    } else {
        if (!valid) return;
    }

    float acc[4] = {0.f, 0.f, 0.f, 0.f};
    int cnt0 = 0;

    if (valid) {
        cnt0 = g_icnt[node];
        const int cnt = min(cnt0, CAP);
        if (!LAYER2 && (threadIdx.x & 63) == 0)
            atomicAdd(&g_cnt[batch[node]], 1.0f);

        addf4(acc, *(const float4*)(g_y + (size_t)node * DH + c));   // self loop

        const int4* ip = (const int4*)(g_eslot + node * CAP);        // CAP%4==0
        int j = 0;
        for (; j + 8 <= cnt; j += 8) {
            int4 sA = ip[j >> 2];
            int4 sB = ip[(j >> 2) + 1];
            float4 v0 = *(const float4*)(g_y + (size_t)sA.x * DH + c);
            float4 v1 = *(const float4*)(g_y + (size_t)sA.y * DH + c);
            float4 v2 = *(const float4*)(g_y + (size_t)sA.z * DH + c);
            float4 v3 = *(const float4*)(g_y + (size_t)sA.w * DH + c);
            float4 v4 = *(const float4*)(g_y + (size_t)sB.x * DH + c);
            float4 v5 = *(const float4*)(g_y + (size_t)sB.y * DH + c);
            float4 v6 = *(const float4*)(g_y + (size_t)sB.z * DH + c);
            float4 v7 = *(const float4*)(g_y + (size_t)sB.w * DH + c);
            addf4(acc, v0); addf4(acc, v1); addf4(acc, v2); addf4(acc, v3);
            addf4(acc, v4); addf4(acc, v5); addf4(acc, v6); addf4(acc, v7);
        }
        if (j + 4 <= cnt) {
            int4 sA = ip[j >> 2];
            float4 v0 = *(const float4*)(g_y + (size_t)sA.x * DH + c);
            float4 v1 = *(const float4*)(g_y + (size_t)sA.y * DH + c);
            float4 v2 = *(const float4*)(g_y + (size_t)sA.z * DH + c);
            float4 v3 = *(const float4*)(g_y + (size_t)sA.w * DH + c);
            addf4(acc, v0); addf4(acc, v1); addf4(acc, v2); addf4(acc, v3);
            j += 4;
        }
        for (; j < cnt; j++) {
            int s = g_eslot[node * CAP + j];
            addf4(acc, *(const float4*)(g_y + (size_t)s * DH + c));
        }
    }

    if (!LAYER2) {
        const float dv = rsqrtf(1.0f + (float)cnt0);
        float4 b = *(const float4*)(bias + c);
        __half2 h01 = __floats2half2_rn(fmaxf(fmaf(acc[0], dv, b.x), 0.f),
                                        fmaxf(fmaf(acc[1], dv, b.y), 0.f));
        __half2 h23 = __floats2half2_rn(fmaxf(fmaf(acc[2], dv, b.z), 0.f),
                                        fmaxf(fmaf(acc[3], dv, b.w), 0.f));
        uint2 u = make_uint2(*(uint32_t*)&h01, *(uint32_t*)&h23);
        *(uint2*)(g_h16 + (size_t)node * DH + c) = u;
    } else {
        if (valid) {
            const float dv = rsqrtf(1.0f + (float)cnt0);
            float4 b = *(const float4*)(bias + c);
            float r[4];
            r[0] = fmaxf(fmaf(acc[0], dv, b.x), 0.f);
            r[1] = fmaxf(fmaf(acc[1], dv, b.y), 0.f);
            r[2] = fmaxf(fmaf(acc[2], dv, b.z), 0.f);
            r[3] = fmaxf(fmaf(acc[3], dv, b.w), 0.f);
            int g = batch[node];
            if (g == sg) {
                #pragma unroll
                for (int i = 0; i < 4; i++) atomicAdd(&sp[c + i], r[i]);
            } else {
                #pragma unroll
                for (int i = 0; i < 4; i++) atomicAdd(&g_pool[(size_t)g * DH + c + i], r[i]);
            }
            if ((threadIdx.x & 63) == 0) g_icnt[node] = 0;   // self-clean for next launch
        }
        __syncthreads();
        atomicAdd(&g_pool[(size_t)sg * DH + threadIdx.x], sp[threadIdx.x]);
    }
}

// ================= final FC (+ scratch clear) =================
__global__ void k_fc(const float* __restrict__ wfc, const float* __restrict__ bfc,
                     float* __restrict__ out)
{
    int w = (blockIdx.x * blockDim.x + threadIdx.x) >> 5;
    int lane = threadIdx.x & 31;
    if (w >= GNUM) return;
    float sum = 0.f;
    #pragma unroll
    for (int j = lane; j < DH; j += 32) {
        sum += g_pool[w * DH + j] * wfc[j];
        g_pool[w * DH + j] = 0.f;          // self-clean
    }
    #pragma unroll
    for (int o = 16; o; o >>= 1)
        sum += __shfl_xor_sync(0xffffffffu, sum, o);
    if (lane == 0) {
        float cntw = g_cnt[w];
        g_cnt[w] = 0.f;                    // self-clean
        out[w] = sum / fmaxf(cntw, 1.f) + bfc[0];
    }
}

// ================= launch =================
extern "C" void kernel_launch(void* const* d_in, const int* in_sizes, int n_in,
                              void* d_out, int out_size)
{
    const float* x     = (const float*)d_in[0];
    const int*   ei    = (const int*)  d_in[1];
    const int*   batch = (const int*)  d_in[2];
    const float* W1    = (const float*)d_in[3];
    const float* b1    = (const float*)d_in[4];
    const float* W2    = (const float*)d_in[5];
    const float* b2    = (const float*)d_in[6];
    const float* wfc   = (const float*)d_in[7];
    const float* bfc   = (const float*)d_in[8];
    float* out = (float*)d_out;

    const int N = in_sizes[2];        // 20000
    const int E = in_sizes[1] / 2;    // 320000
    const int* src = ei;
    const int* dst = ei + E;

    cudaFuncSetAttribute(k_gemm_h<DIN>,
                         cudaFuncAttributeMaxDynamicSharedMemorySize, SMEM_GEMM_BYTES);
    cudaFuncSetAttribute(k_gemm_h<DH>,
                         cudaFuncAttributeMaxDynamicSharedMemorySize, SMEM_GEMM_BYTES);

    // fused prep: CSR fill + x->fp16 + W1/W2 transpose->fp16
    const int FILL_B = (E + 255) / 256;
    const int X16_B  = (N * DIN / 4 + 255) / 256;
    const int W1T_B  = (DIN / 32) * (DH / 32);
    const int W2T_B  = (DH / 32) * (DH / 32);
    k_prep<<<FILL_B + X16_B + W1T_B + W2T_B, 256>>>(src, dst, x, W1, W2, E, N);

    __half* x16; cudaGetSymbolAddress((void**)&x16, g_x16);
    __half* w1t; cudaGetSymbolAddress((void**)&w1t, g_w1t);
    __half* w2t; cudaGetSymbolAddress((void**)&w2t, g_w2t);
    __half* h16; cudaGetSymbolAddress((void**)&h16, g_h16);

    const int gemm_blocks = (N + 159) / 160;   // 125
    const int gat_blocks  = (N + 3) / 4;

    // layer 1
    k_gemm_h<DIN><<<gemm_blocks, 640, SMEM_GEMM_BYTES>>>(x16, w1t, N);
    k_gather<false><<<gat_blocks, 256>>>(batch, b1, N);

    // layer 2
    k_gemm_h<DH><<<gemm_blocks, 640, SMEM_GEMM_BYTES>>>(h16, w2t, N);
    k_gather<true><<<gat_blocks, 256>>>(batch, b2, N);

    // fc (also clears pool/cnt for next launch)
    k_fc<<<GNUM * 32 / 128, 128>>>(wfc, bfc, out);
}